// round 1
// baseline (speedup 1.0000x reference)
#include <cuda_runtime.h>

// Problem constants
#define BNUM   1024
#define QNUM   96
#define CNUM   16
#define HNUM   100
#define NSTEPS_K 100
#define QP1    97            // Q+1 (state features per row)
#define ROWS   (BNUM*CNUM)   // 16384 independent rows
#define MT     128           // rows per CTA
#define NTHREADS 256         // 16x16
#define RM     8             // rows per thread
#define RN     7             // outputs per thread (16*7 = 112 >= 100)
#define XSTR   129           // padded row stride (floats) -> conflict-free

// Shared memory layout (float offsets)
#define OFF_XS   0
#define SZ_XS    (QP1*XSTR)            // 97*129  = 12513
#define OFF_HS   (OFF_XS + SZ_XS)
#define SZ_HS    (HNUM*XSTR)           // 100*129 = 12900
#define OFF_W1   (OFF_HS + SZ_HS)
#define SZ_W1    (QP1*HNUM)            // 9700  (K-major, k<97)
#define OFF_W1T  (OFF_W1 + SZ_W1)      // t-column of W1, 100
#define OFF_W2   (OFF_W1T + HNUM)
#define SZ_W2    (HNUM*HNUM)           // 10000 (K-major)
#define OFF_W3   (OFF_W2 + SZ_W2)
#define SZ_W3    (HNUM*QP1)            // 9700  (K-major)
#define OFF_B1   (OFF_W3 + SZ_W3)
#define OFF_B2   (OFF_B1 + HNUM)
#define OFF_B3   (OFF_B2 + HNUM)
#define SMEM_FLOATS (OFF_B3 + QP1)     // 55210 floats
#define SMEM_BYTES  (SMEM_FLOATS * 4)  // 220840 B (fits 227KB opt-in)

extern __shared__ float smem[];

__global__ __launch_bounds__(NTHREADS, 1)
void arima_flow_kernel(const float* __restrict__ series,
                       const float* __restrict__ rand_error,
                       const float* __restrict__ W1, const float* __restrict__ b1,
                       const float* __restrict__ W2, const float* __restrict__ b2,
                       const float* __restrict__ W3, const float* __restrict__ b3,
                       float* __restrict__ out)
{
    float* Xs  = smem + OFF_XS;   // [QP1][XSTR]  current state, K-major
    float* Hs  = smem + OFF_HS;   // [HNUM][XSTR] hidden activations, K-major
    float* W1s = smem + OFF_W1;   // [97][100]    W1[j][k] stored as [k][j]
    float* W1t = smem + OFF_W1T;  // [100]        W1[j][97] (t column)
    float* W2s = smem + OFF_W2;   // [100][100]
    float* W3s = smem + OFF_W3;   // [100][97]
    float* B1s = smem + OFF_B1;
    float* B2s = smem + OFF_B2;
    float* B3s = smem + OFF_B3;

    const int tid  = threadIdx.x;
    const int tx   = tid & 15;      // output-tile coordinate
    const int ty   = tid >> 4;      // row-tile coordinate
    const int row0 = ty * RM;       // 0..120
    const int base = blockIdx.x * MT;

    // ---- load weights, transposed to K-major ----
    for (int idx = tid; idx < HNUM * QP1; idx += NTHREADS) {
        int j = idx / QP1, k = idx - j * QP1;
        W1s[k * HNUM + j] = W1[j * (QNUM + 2) + k];
    }
    for (int j = tid; j < HNUM; j += NTHREADS) {
        W1t[j] = W1[j * (QNUM + 2) + (QNUM + 1)];
        B1s[j] = b1[j];
        B2s[j] = b2[j];
    }
    for (int idx = tid; idx < HNUM * HNUM; idx += NTHREADS) {
        int j = idx / HNUM, k = idx - j * HNUM;
        W2s[k * HNUM + j] = W2[idx];
    }
    for (int idx = tid; idx < QP1 * HNUM; idx += NTHREADS) {
        int j = idx / HNUM, k = idx - j * HNUM;  // j<97 output, k<100 hidden
        W3s[k * QP1 + j] = W3[idx];
    }
    for (int j = tid; j < QP1; j += NTHREADS) B3s[j] = b3[j];

    // ---- load x0 = cat(series, rand_error) into Xs (K-major over feature q) ----
    for (int idx = tid; idx < QP1 * MT; idx += NTHREADS) {
        int q = idx / MT, m = idx - q * MT;
        int row = base + m;
        int b = row >> 4, c = row & 15;
        float v = (q < QNUM) ? series[(b * QNUM + q) * CNUM + c]
                             : rand_error[b * CNUM + c];
        Xs[q * XSTR + m] = v;
    }
    __syncthreads();

    // ---- per-thread tile constants: output columns + noise snapshot ----
    int colh[RN], colq[RN];
    bool vh[RN], vq[RN];
    float noise[RM][RN];
    #pragma unroll
    for (int i = 0; i < RN; i++) {
        int j = i * 16 + tx;
        vh[i] = (j < HNUM); colh[i] = vh[i] ? j : 0;
        vq[i] = (j < QP1);  colq[i] = vq[i] ? j : 0;
        #pragma unroll
        for (int r = 0; r < RM; r++)
            noise[r][i] = Xs[colq[i] * XSTR + row0 + r];
    }

    const float dt = 1.0f / (float)NSTEPS_K;
    float acc[RM][RN];

    for (int s = 0; s < NSTEPS_K; s++) {
        const float t = (float)s / (float)NSTEPS_K;
        __syncthreads();  // [A] Xs stable, Hs free

        // ===== Layer 1: h1 = tanh(X @ W1^T + b1 + t * W1[:,97]) =====
        #pragma unroll
        for (int i = 0; i < RN; i++) {
            float bt = fmaf(t, W1t[colh[i]], B1s[colh[i]]);
            #pragma unroll
            for (int r = 0; r < RM; r++) acc[r][i] = bt;
        }
        {
            const float* Xp = Xs + row0;
            const float* Wp = W1s;
            #pragma unroll 2
            for (int k = 0; k < QP1; k++) {
                float a[RM], bb[RN];
                #pragma unroll
                for (int r = 0; r < RM; r++) a[r] = Xp[r];
                #pragma unroll
                for (int i = 0; i < RN; i++) bb[i] = Wp[colh[i]];
                #pragma unroll
                for (int r = 0; r < RM; r++)
                    #pragma unroll
                    for (int i = 0; i < RN; i++)
                        acc[r][i] = fmaf(a[r], bb[i], acc[r][i]);
                Xp += XSTR; Wp += HNUM;
            }
        }
        #pragma unroll
        for (int i = 0; i < RN; i++) {
            if (vh[i]) {
                #pragma unroll
                for (int r = 0; r < RM; r++)
                    Hs[colh[i] * XSTR + row0 + r] = tanhf(acc[r][i]);
            }
        }
        __syncthreads();  // [B] h1 visible

        // ===== Layer 2: h2 = tanh(h1 @ W2^T + b2) =====
        #pragma unroll
        for (int i = 0; i < RN; i++) {
            float bt = B2s[colh[i]];
            #pragma unroll
            for (int r = 0; r < RM; r++) acc[r][i] = bt;
        }
        {
            const float* Hp = Hs + row0;
            const float* Wp = W2s;
            #pragma unroll 2
            for (int k = 0; k < HNUM; k++) {
                float a[RM], bb[RN];
                #pragma unroll
                for (int r = 0; r < RM; r++) a[r] = Hp[r];
                #pragma unroll
                for (int i = 0; i < RN; i++) bb[i] = Wp[colh[i]];
                #pragma unroll
                for (int r = 0; r < RM; r++)
                    #pragma unroll
                    for (int i = 0; i < RN; i++)
                        acc[r][i] = fmaf(a[r], bb[i], acc[r][i]);
                Hp += XSTR; Wp += HNUM;
            }
        }
        #pragma unroll
        for (int i = 0; i < RN; i++)
            #pragma unroll
            for (int r = 0; r < RM; r++)
                acc[r][i] = tanhf(acc[r][i]);
        __syncthreads();  // [C] all readers of h1 done
        #pragma unroll
        for (int i = 0; i < RN; i++) {
            if (vh[i]) {
                #pragma unroll
                for (int r = 0; r < RM; r++)
                    Hs[colh[i] * XSTR + row0 + r] = acc[r][i];
            }
        }
        __syncthreads();  // [D] h2 visible

        // ===== Layer 3 + Euler update: x += (h2 @ W3^T + b3 - noise) * dt =====
        #pragma unroll
        for (int i = 0; i < RN; i++) {
            float bt = B3s[colq[i]];
            #pragma unroll
            for (int r = 0; r < RM; r++) acc[r][i] = bt;
        }
        {
            const float* Hp = Hs + row0;
            const float* Wp = W3s;
            #pragma unroll 2
            for (int k = 0; k < HNUM; k++) {
                float a[RM], bb[RN];
                #pragma unroll
                for (int r = 0; r < RM; r++) a[r] = Hp[r];
                #pragma unroll
                for (int i = 0; i < RN; i++) bb[i] = Wp[colq[i]];
                #pragma unroll
                for (int r = 0; r < RM; r++)
                    #pragma unroll
                    for (int i = 0; i < RN; i++)
                        acc[r][i] = fmaf(a[r], bb[i], acc[r][i]);
                Hp += XSTR; Wp += QP1;
            }
        }
        #pragma unroll
        for (int i = 0; i < RN; i++) {
            if (vq[i]) {
                #pragma unroll
                for (int r = 0; r < RM; r++) {
                    int off = colq[i] * XSTR + row0 + r;
                    Xs[off] = fmaf(acc[r][i] - noise[r][i], dt, Xs[off]);
                }
            }
        }
        // next iteration's [A] sync protects Xs
    }

    __syncthreads();
    // ---- write result back to (B, 97, C) layout ----
    for (int idx = tid; idx < QP1 * MT; idx += NTHREADS) {
        int q = idx / MT, m = idx - q * MT;
        int row = base + m;
        int b = row >> 4, c = row & 15;
        out[(b * QP1 + q) * CNUM + c] = Xs[q * XSTR + m];
    }
}

extern "C" void kernel_launch(void* const* d_in, const int* in_sizes, int n_in,
                              void* d_out, int out_size)
{
    const float* series     = (const float*)d_in[0];
    const float* rand_error = (const float*)d_in[1];
    const float* W1 = (const float*)d_in[2];
    const float* b1 = (const float*)d_in[3];
    const float* W2 = (const float*)d_in[4];
    const float* b2 = (const float*)d_in[5];
    const float* W3 = (const float*)d_in[6];
    const float* b3 = (const float*)d_in[7];
    float* out = (float*)d_out;

    cudaFuncSetAttribute(arima_flow_kernel,
                         cudaFuncAttributeMaxDynamicSharedMemorySize, SMEM_BYTES);
    arima_flow_kernel<<<ROWS / MT, NTHREADS, SMEM_BYTES>>>(
        series, rand_error, W1, b1, W2, b2, W3, b3, out);
}

// round 3
// speedup vs baseline: 1.2953x; 1.2953x over previous
#include <cuda_runtime.h>
#include <cstdint>

// Problem constants
#define BNUM   1024
#define QNUM   96
#define CNUM   16
#define HNUM   100
#define NSTEPS_K 100
#define QP1    97            // Q+1 state features per row
#define ROWS   (BNUM*CNUM)   // 16384 independent rows
#define MT     128           // rows per CTA
#define NTHREADS 256         // 16x16
#define RM     8             // rows per thread (4 float2 pairs)
#define RN     7             // output cols per thread (16*7=112 >= 100)

typedef unsigned int       u32t;
typedef unsigned long long u64t;

// Activation layout: col-major, stride 128, row-rotated by (col&7)*4 to kill
// the 16-column-stride store conflicts while keeping 16B-aligned vector reads.
//   elem(col,row) at  col*128 + ((row + ((col&7)<<2)) & 127)
#define ASTR 128

// Shared memory layout (float offsets)
#define OFF_XS   0
#define SZ_XS    (QP1*ASTR)            // 12416
#define OFF_HS   (OFF_XS + SZ_XS)      // 12416
#define SZ_HS    (HNUM*ASTR)           // 12800
#define OFF_W1   (OFF_HS + SZ_HS)      // 25216
#define SZ_W1    (QP1*HNUM)            // 9700  K-major [k][j]
#define OFF_W1T  (OFF_W1 + SZ_W1)      // 34916 (t column of W1, 100)
#define OFF_W2   (OFF_W1T + HNUM)      // 35016
#define SZ_W2    (HNUM*HNUM)           // 10000
#define OFF_W3   (OFF_W2 + SZ_W2)      // 45016
#define SZ_W3    (HNUM*QP1)            // 9700
#define OFF_B1   (OFF_W3 + SZ_W3)      // 54716
#define OFF_B2   (OFF_B1 + HNUM)
#define OFF_B3   (OFF_B2 + HNUM)
#define SMEM_FLOATS (OFF_B3 + QP1)     // 55013 floats
#define SMEM_BYTES  (SMEM_FLOATS * 4)  // 220052 B

extern __shared__ float smem[];

__device__ __forceinline__ void fma2(u64t& d, u64t a, u64t b) {
    asm("fma.rn.f32x2 %0, %1, %2, %0;" : "+l"(d) : "l"(a), "l"(b));
}
__device__ __forceinline__ u64t dup2(float w) {
    u64t r;
    asm("mov.b64 %0, {%1, %1};" : "=l"(r) : "f"(w));
    return r;
}
__device__ __forceinline__ void unpack2(u64t v, float& lo, float& hi) {
    asm("mov.b64 {%0, %1}, %2;" : "=f"(lo), "=f"(hi) : "l"(v));
}
__device__ __forceinline__ float tanh_fast(float x) {
    asm("tanh.approx.f32 %0, %0;" : "+f"(x));
    return x;
}
__device__ __forceinline__ void lds_v2u64(u32t addr, u64t& a, u64t& b) {
    asm("ld.shared.v2.b64 {%0, %1}, [%2];" : "=l"(a), "=l"(b) : "r"(addr));
}
__device__ __forceinline__ void sts_v2f32(u32t addr, float lo, float hi) {
    asm volatile("st.shared.v2.f32 [%0], {%1, %2};" :: "r"(addr), "f"(lo), "f"(hi));
}

__device__ __forceinline__ int aoff(int col, int row) {
    return col * ASTR + ((row + ((col & 7) << 2)) & 127);
}

// K-loop GEMM micro-kernel: acc[4][RN] (row-pairs x cols) += A[k][rows] * W[k][col]
template<int KTOT, int WS>
__device__ __forceinline__ void gemm_tile(u32t a_u32, const float* __restrict__ Wp,
                                          const int (&col)[RN],
                                          const int (&g0a)[8], const int (&g1a)[8],
                                          u64t (&acc)[4][RN])
{
    int k = 0;
    u32t xaddr = a_u32;
    #pragma unroll 1
    for (; k + 8 <= KTOT; k += 8, xaddr += 8 * ASTR * 4, Wp += 8 * WS) {
        #pragma unroll
        for (int u = 0; u < 8; u++) {
            u64t a0, a1, a2_, a3;
            lds_v2u64(xaddr + g0a[u], a0, a1);
            lds_v2u64(xaddr + g1a[u], a2_, a3);
            #pragma unroll
            for (int i = 0; i < RN; i++) {
                u64t b2 = dup2(Wp[u * WS + col[i]]);
                fma2(acc[0][i], a0, b2);
                fma2(acc[1][i], a1, b2);
                fma2(acc[2][i], a2_, b2);
                fma2(acc[3][i], a3, b2);
            }
        }
    }
    // remainder (KTOT % 8 iters; k is multiple of 8 so swizzle tables still apply)
    constexpr int REM = KTOT & 7;
    #pragma unroll
    for (int u = 0; u < REM; u++) {
        u64t a0, a1, a2_, a3;
        lds_v2u64(xaddr + g0a[u], a0, a1);
        lds_v2u64(xaddr + g1a[u], a2_, a3);
        #pragma unroll
        for (int i = 0; i < RN; i++) {
            u64t b2 = dup2(Wp[u * WS + col[i]]);
            fma2(acc[0][i], a0, b2);
            fma2(acc[1][i], a1, b2);
            fma2(acc[2][i], a2_, b2);
            fma2(acc[3][i], a3, b2);
        }
    }
}

__global__ __launch_bounds__(NTHREADS, 1)
void arima_flow_kernel(const float* __restrict__ series,
                       const float* __restrict__ rand_error,
                       const float* __restrict__ W1, const float* __restrict__ b1,
                       const float* __restrict__ W2, const float* __restrict__ b2,
                       const float* __restrict__ W3, const float* __restrict__ b3,
                       float* __restrict__ out)
{
    float* Xs  = smem + OFF_XS;
    float* W1s = smem + OFF_W1;
    float* W1t = smem + OFF_W1T;
    float* W2s = smem + OFF_W2;
    float* W3s = smem + OFF_W3;
    float* B1s = smem + OFF_B1;
    float* B2s = smem + OFF_B2;
    float* B3s = smem + OFF_B3;

    u32t sb;
    asm("{ .reg .u64 t; cvta.to.shared.u64 t, %1; cvt.u32.u64 %0, t; }"
        : "=r"(sb) : "l"(smem));
    const u32t XS_U = sb + OFF_XS * 4;
    const u32t HS_U = sb + OFF_HS * 4;

    const int tid  = threadIdx.x;
    const int tx   = tid & 15;
    const int ty   = tid >> 4;
    const int row0 = ty * RM;
    const int base = blockIdx.x * MT;

    // ---- load weights (transpose to K-major) ----
    for (int idx = tid; idx < HNUM * QP1; idx += NTHREADS) {
        int j = idx / QP1, k = idx - j * QP1;
        W1s[k * HNUM + j] = W1[j * (QNUM + 2) + k];
    }
    for (int j = tid; j < HNUM; j += NTHREADS) {
        W1t[j] = W1[j * (QNUM + 2) + (QNUM + 1)];
        B1s[j] = b1[j];
        B2s[j] = b2[j];
    }
    for (int idx = tid; idx < HNUM * HNUM; idx += NTHREADS) {
        int j = idx / HNUM, k = idx - j * HNUM;
        W2s[k * HNUM + j] = W2[idx];
    }
    for (int idx = tid; idx < QP1 * HNUM; idx += NTHREADS) {
        int j = idx / HNUM, k = idx - j * HNUM;
        W3s[k * QP1 + j] = W3[idx];
    }
    for (int j = tid; j < QP1; j += NTHREADS) B3s[j] = b3[j];

    // ---- x0 = cat(series, rand_error) into swizzled Xs ----
    for (int idx = tid; idx < QP1 * MT; idx += NTHREADS) {
        int q = idx / MT, m = idx - q * MT;
        int row = base + m;
        int b = row >> 4, c = row & 15;
        float v = (q < QNUM) ? series[(b * QNUM + q) * CNUM + c]
                             : rand_error[b * CNUM + c];
        Xs[aoff(q, m)] = v;
    }
    __syncthreads();

    // ---- per-thread constants ----
    int colh[RN], colq[RN];
    bool vh[RN], vq[RN];
    #pragma unroll
    for (int i = 0; i < RN; i++) {
        int j = i * 16 + tx;
        vh[i] = (j < HNUM); colh[i] = vh[i] ? j : 0;
        vq[i] = (j < QP1);  colq[i] = vq[i] ? j : 0;
    }
    // swizzle tables: byte offsets of the two 4-row groups for each (k&7)
    int g0a[8], g1a[8];
    #pragma unroll
    for (int u = 0; u < 8; u++) {
        g0a[u] = ((row0     + 4 * u) & 127) * 4 + u * ASTR * 4;
        g1a[u] = ((row0 + 4 + 4 * u) & 127) * 4 + u * ASTR * 4;
    }
    // store-side swizzle: all of this thread's cols share col&7 == tx&7
    const int swzc = (tx & 7) << 2;
    int rowoff[4];
    #pragma unroll
    for (int r2 = 0; r2 < 4; r2++)
        rowoff[r2] = ((row0 + 2 * r2 + swzc) & 127) * 4;

    // noise snapshot
    float noise[RM][RN];
    #pragma unroll
    for (int i = 0; i < RN; i++)
        #pragma unroll
        for (int r = 0; r < RM; r++)
            noise[r][i] = Xs[aoff(colq[i], row0 + r)];

    const float dt = 1.0f / (float)NSTEPS_K;
    u64t acc[4][RN];

    for (int s = 0; s < NSTEPS_K; s++) {
        const float t = (float)s / (float)NSTEPS_K;
        __syncthreads();  // [A] Xs stable, Hs free

        // ===== Layer 1: h1 = tanh(X @ W1^T + b1 + t*W1t) =====
        #pragma unroll
        for (int i = 0; i < RN; i++) {
            float bt = fmaf(t, W1t[colh[i]], B1s[colh[i]]);
            u64t b2 = dup2(bt);
            #pragma unroll
            for (int r2 = 0; r2 < 4; r2++) acc[r2][i] = b2;
        }
        gemm_tile<QP1, HNUM>(XS_U, W1s, colh, g0a, g1a, acc);
        #pragma unroll
        for (int i = 0; i < RN; i++) {
            if (vh[i]) {
                u32t cbase = HS_U + colh[i] * (ASTR * 4);
                #pragma unroll
                for (int r2 = 0; r2 < 4; r2++) {
                    float lo, hi; unpack2(acc[r2][i], lo, hi);
                    sts_v2f32(cbase + rowoff[r2], tanh_fast(lo), tanh_fast(hi));
                }
            }
        }
        __syncthreads();  // [B] h1 visible

        // ===== Layer 2: h2 = tanh(h1 @ W2^T + b2) =====
        #pragma unroll
        for (int i = 0; i < RN; i++) {
            u64t b2 = dup2(B2s[colh[i]]);
            #pragma unroll
            for (int r2 = 0; r2 < 4; r2++) acc[r2][i] = b2;
        }
        gemm_tile<HNUM, HNUM>(HS_U, W2s, colh, g0a, g1a, acc);
        // tanh in regs, then sync so all h1 readers finish before overwrite
        float h2lo[4][RN], h2hi[4][RN];
        #pragma unroll
        for (int i = 0; i < RN; i++)
            #pragma unroll
            for (int r2 = 0; r2 < 4; r2++) {
                float lo, hi; unpack2(acc[r2][i], lo, hi);
                h2lo[r2][i] = tanh_fast(lo);
                h2hi[r2][i] = tanh_fast(hi);
            }
        __syncthreads();  // [C]
        #pragma unroll
        for (int i = 0; i < RN; i++) {
            if (vh[i]) {
                u32t cbase = HS_U + colh[i] * (ASTR * 4);
                #pragma unroll
                for (int r2 = 0; r2 < 4; r2++)
                    sts_v2f32(cbase + rowoff[r2], h2lo[r2][i], h2hi[r2][i]);
            }
        }
        __syncthreads();  // [D] h2 visible

        // ===== Layer 3 + Euler: x += (h2 @ W3^T + b3 - noise) * dt =====
        #pragma unroll
        for (int i = 0; i < RN; i++) {
            u64t b2 = dup2(B3s[colq[i]]);
            #pragma unroll
            for (int r2 = 0; r2 < 4; r2++) acc[r2][i] = b2;
        }
        gemm_tile<HNUM, QP1>(HS_U, W3s, colq, g0a, g1a, acc);
        #pragma unroll
        for (int i = 0; i < RN; i++) {
            if (vq[i]) {
                u32t cbase = XS_U + colq[i] * (ASTR * 4);
                #pragma unroll
                for (int r2 = 0; r2 < 4; r2++) {
                    u32t addr = cbase + rowoff[r2];
                    float plo, phi; unpack2(acc[r2][i], plo, phi);
                    float xlo, xhi;
                    asm("ld.shared.v2.f32 {%0, %1}, [%2];"
                        : "=f"(xlo), "=f"(xhi) : "r"(addr));
                    xlo = fmaf(plo - noise[2 * r2][i],     dt, xlo);
                    xhi = fmaf(phi - noise[2 * r2 + 1][i], dt, xhi);
                    sts_v2f32(addr, xlo, xhi);
                }
            }
        }
        // next iteration's [A] protects Xs
    }

    __syncthreads();
    // ---- write result (B, 97, C) ----
    for (int idx = tid; idx < QP1 * MT; idx += NTHREADS) {
        int q = idx / MT, m = idx - q * MT;
        int row = base + m;
        int b = row >> 4, c = row & 15;
        out[(b * QP1 + q) * CNUM + c] = Xs[aoff(q, m)];
    }
}

extern "C" void kernel_launch(void* const* d_in, const int* in_sizes, int n_in,
                              void* d_out, int out_size)
{
    const float* series     = (const float*)d_in[0];
    const float* rand_error = (const float*)d_in[1];
    const float* W1 = (const float*)d_in[2];
    const float* b1 = (const float*)d_in[3];
    const float* W2 = (const float*)d_in[4];
    const float* b2 = (const float*)d_in[5];
    const float* W3 = (const float*)d_in[6];
    const float* b3 = (const float*)d_in[7];
    float* out = (float*)d_out;

    cudaFuncSetAttribute(arima_flow_kernel,
                         cudaFuncAttributeMaxDynamicSharedMemorySize, SMEM_BYTES);
    arima_flow_kernel<<<ROWS / MT, NTHREADS, SMEM_BYTES>>>(
        series, rand_error, W1, b1, W2, b2, W3, b3, out);
}